// round 1
// baseline (speedup 1.0000x reference)
#include <cuda_runtime.h>

#define N_ATOMS 320
#define RC 6.0f
#define NTHREADS 256
#define NWARPS (NTHREADS / 32)

__global__ __launch_bounds__(NTHREADS, 4)
void featurizer_kernel(const float* __restrict__ atomic_numbers,
                       const float* __restrict__ coords,
                       float* __restrict__ out)
{
    __shared__ float scx[N_ATOMS], scy[N_ATOMS], scz[N_ATOMS];
    __shared__ float ndx[N_ATOMS], ndy[N_ATOMS], ndz[N_ATOMS];
    __shared__ float nr[N_ATOMS], nfc[N_ATOMS], nr2[N_ATOMS];
    __shared__ int   sM;
    __shared__ float sRed[NWARPS * 13];

    const int i    = blockIdx.x;
    const int tid  = threadIdx.x;
    const int lane = tid & 31;
    const int warp = tid >> 5;

    // Stage coordinates in SMEM
    for (int j = tid; j < N_ATOMS; j += NTHREADS) {
        scx[j] = coords[3 * j + 0];
        scy[j] = coords[3 * j + 1];
        scz[j] = coords[3 * j + 2];
    }
    __syncthreads();

    const float xi = scx[i], yi = scy[i], zi = scz[i];
    const float PI_RC = 0.5235987755982988f; // pi / 6

    // ---------------- Phase 1: radial sums (G1, G2 x8, G3 x4) ----------------
    float rad[13];
    #pragma unroll
    for (int q = 0; q < 13; q++) rad[q] = 0.f;

    for (int j = tid; j < N_ATOMS; j += NTHREADS) {
        if (j == i) continue;
        float dx = xi - scx[j], dy = yi - scy[j], dz = zi - scz[j];
        float r2 = dx * dx + dy * dy + dz * dz;
        float r  = sqrtf(r2);
        if (r >= RC) continue;
        float fc = 0.5f * (__cosf(PI_RC * r) + 1.f);
        rad[0] += fc;
        // G2, r_s = 0: eta = 0.5,1,2,4 via powers of exp(-0.5 r^2)
        float e05 = __expf(-0.5f * r2);
        float e1 = e05 * e05, e2 = e1 * e1, e4 = e2 * e2;
        rad[1] += e05 * fc; rad[2] += e1 * fc; rad[3] += e2 * fc; rad[4] += e4 * fc;
        // G2, r_s = 3
        float d3 = r - 3.f; float u = d3 * d3;
        float f05 = __expf(-0.5f * u);
        float f1 = f05 * f05, f2 = f1 * f1, f4 = f2 * f2;
        rad[5] += f05 * fc; rad[6] += f1 * fc; rad[7] += f2 * fc; rad[8] += f4 * fc;
        // G3: cos(kappa r), kappa = 0.5,1,1.5,2
        rad[9]  += __cosf(0.5f * r) * fc;
        rad[10] += __cosf(r) * fc;
        rad[11] += __cosf(1.5f * r) * fc;
        rad[12] += __cosf(2.f * r) * fc;
    }

    // Warp 0: deterministic order-preserving neighbor-list compaction
    if (warp == 0) {
        int base = 0;
        for (int j0 = 0; j0 < N_ATOMS; j0 += 32) {
            int j = j0 + lane;                 // 320 is a multiple of 32
            float dx = xi - scx[j], dy = yi - scy[j], dz = zi - scz[j];
            float r2 = dx * dx + dy * dy + dz * dz;
            float r  = sqrtf(r2);
            bool pred = (j != i) && (r < RC);
            unsigned mask = __ballot_sync(0xffffffffu, pred);
            int pos = base + __popc(mask & ((1u << lane) - 1u));
            if (pred) {
                ndx[pos] = dx; ndy[pos] = dy; ndz[pos] = dz;
                nr[pos] = r; nr2[pos] = r2;
                nfc[pos] = 0.5f * (__cosf(PI_RC * r) + 1.f);
            }
            base += __popc(mask);
        }
        if (lane == 0) sM = base;
    }

    // Reduce radial partials
    #pragma unroll
    for (int q = 0; q < 13; q++) {
        float v = rad[q];
        #pragma unroll
        for (int off = 16; off > 0; off >>= 1) v += __shfl_down_sync(0xffffffffu, v, off);
        if (lane == 0) sRed[warp * 13 + q] = v;
    }
    __syncthreads();

    if (tid == 0) {
        out[i * 22 + 0] = atomic_numbers[i];
        #pragma unroll
        for (int q = 0; q < 13; q++) {
            float s = 0.f;
            #pragma unroll
            for (int w = 0; w < NWARPS; w++) s += sRed[w * 13 + q];
            out[i * 22 + 1 + q] = s;
        }
    }
    const int M = sM;      // valid: written before the __syncthreads above
    __syncthreads();       // protect sRed before reuse in phase 2

    // ---------------- Phase 2: angular sums (G4 x4, G5 x4) ----------------
    float s[8];
    #pragma unroll
    for (int q = 0; q < 8; q++) s[q] = 0.f;

    const int MM = M * M;
    for (int p = tid; p < MM; p += NTHREADS) {
        int a = p / M;
        int b = p - a * M;
        if (a == b) continue;
        float dxa = ndx[a], dya = ndy[a], dza = ndz[a];
        float dxb = ndx[b], dyb = ndy[b], dzb = ndz[b];
        float dot = dxa * dxb + dya * dyb + dza * dzb;
        float rr  = nr[a] * nr[b];
        float cosv = dot / (rr > 0.f ? rr : 1.f);
        float R2p = nr2[a] + nr2[b];
        float ex = dxa - dxb, ey = dya - dyb, ez = dza - dzb;
        float r2jk = ex * ex + ey * ey + ez * ez;
        float rjk  = sqrtf(r2jk);
        float fcjk = (rjk < RC) ? 0.5f * (__cosf(PI_RC * rjk) + 1.f) : 0.f;
        float fc2 = nfc[a] * nfc[b];
        float fc3 = fc2 * fcjk;
        float ep1 = __expf(-0.1f * R2p);
        float ep5 = __expf(-0.5f * R2p);
        float et1 = ep1 * __expf(-0.1f * r2jk);
        float et5 = ep5 * __expf(-0.5f * r2jk);
        float op = 1.f + cosv, om = 1.f - cosv;
        float a1 = om * om;          // (1-c)^2
        float op2 = op * op;
        float a2 = op2 * op2;        // (1+c)^4
        float a3 = a1 * a1;          // (1-c)^4
        float w41 = et1 * fc3, w45 = et5 * fc3;
        float w51 = ep1 * fc2, w55 = ep5 * fc2;
        s[0] += op * w41; s[1] += a1 * w41; s[2] += a2 * w45; s[3] += a3 * w45;
        s[4] += op * w51; s[5] += a1 * w51; s[6] += a2 * w55; s[7] += a3 * w55;
    }

    #pragma unroll
    for (int q = 0; q < 8; q++) {
        float v = s[q];
        #pragma unroll
        for (int off = 16; off > 0; off >>= 1) v += __shfl_down_sync(0xffffffffu, v, off);
        if (lane == 0) sRed[warp * 8 + q] = v;
    }
    __syncthreads();

    if (tid == 0) {
        const float scale[4] = {0.5f, 0.25f, 0.0625f, 0.0625f};
        #pragma unroll
        for (int q = 0; q < 8; q++) {
            float v = 0.f;
            #pragma unroll
            for (int w = 0; w < NWARPS; w++) v += sRed[w * 8 + q];
            int col = (q < 4) ? (14 + q) : (18 + (q - 4));
            out[i * 22 + col] = v * scale[q & 3];
        }
    }
}

extern "C" void kernel_launch(void* const* d_in, const int* in_sizes, int n_in,
                              void* d_out, int out_size)
{
    const float* atomic_numbers = (const float*)d_in[0]; // [320,1]
    const float* coordinates    = (const float*)d_in[1]; // [320,3]
    float* out = (float*)d_out;                          // [320,22]
    featurizer_kernel<<<N_ATOMS, NTHREADS>>>(atomic_numbers, coordinates, out);
}

// round 2
// speedup vs baseline: 1.1335x; 1.1335x over previous
#include <cuda_runtime.h>

#define N_ATOMS 320
#define NTHREADS 256
#define NWARPS 8
#define NCHUNK 10          // 320 / 32 mask words

// cos(sqrt(y)), degree-9 Taylor in y; |err| < 4e-9 for y in [0, pi^2]
__device__ __forceinline__ float cos_sqrt_poly(float y) {
    float p = -1.56192070e-16f;
    p = fmaf(p, y,  4.77947733e-14f);
    p = fmaf(p, y, -1.14707456e-11f);
    p = fmaf(p, y,  2.08767570e-9f);
    p = fmaf(p, y, -2.75573192e-7f);
    p = fmaf(p, y,  2.48015873e-5f);
    p = fmaf(p, y, -1.38888889e-3f);
    p = fmaf(p, y,  4.16666667e-2f);
    p = fmaf(p, y, -0.5f);
    p = fmaf(p, y,  1.0f);
    return p;
}

__global__ __launch_bounds__(NTHREADS, 3)
void featurizer_kernel(const float* __restrict__ atomic_numbers,
                       const float* __restrict__ coords,
                       float* __restrict__ out)
{
    __shared__ float scx[N_ATOMS], scy[N_ATOMS], scz[N_ATOMS];
    // per-j neighbor data (indexed by original j)
    __shared__ float sdx[N_ATOMS], sdy[N_ATOMS], sdz[N_ATOMS];
    __shared__ float sr2[N_ATOMS], sfc[N_ATOMS], se1[N_ATOMS], se5[N_ATOMS], sir[N_ATOMS];
    __shared__ int   slist[N_ATOMS];
    __shared__ unsigned smask[NCHUNK];
    __shared__ float sRedA[NWARPS * 13];
    __shared__ float sRedB[NWARPS * 8];

    const int i    = blockIdx.x;
    const int tid  = threadIdx.x;
    const int lane = tid & 31;
    const int warp = tid >> 5;

    for (int j = tid; j < N_ATOMS; j += NTHREADS) {
        scx[j] = coords[3 * j + 0];
        scy[j] = coords[3 * j + 1];
        scz[j] = coords[3 * j + 2];
    }
    __syncthreads();

    const float xi = scx[i], yi = scy[i], zi = scz[i];
    const float PI2_36 = 0.27415567780803773f;   // (pi/6)^2

    // ---- Phase 1: radial sums + per-neighbor arrays + ballot masks ----
    float rad[13];
    #pragma unroll
    for (int q = 0; q < 13; q++) rad[q] = 0.f;

    for (int j = tid; j < N_ATOMS; j += NTHREADS) {
        float dx = xi - scx[j], dy = yi - scy[j], dz = zi - scz[j];
        float r2 = dx * dx + dy * dy + dz * dz;
        bool pred = (j != i) && (r2 < 36.0f);
        unsigned m = __ballot_sync(0xffffffffu, pred);
        if (lane == 0) smask[j >> 5] = m;
        if (pred) {
            float rs   = rsqrtf(r2);
            float r    = r2 * rs;
            float fc   = 0.5f * (cos_sqrt_poly(PI2_36 * r2) + 1.0f);
            float e05  = __expf(-0.5f * r2);                 // exp(-0.5 r^2)
            float e1g2 = e05 * e05, e2g2 = e1g2 * e1g2, e4g2 = e2g2 * e2g2;
            float gsh  = __expf(fmaf(3.0f, r, -4.5f));       // exp(3r-4.5)
            float f05  = e05 * gsh;                          // exp(-0.5 (r-3)^2)
            float f1 = f05 * f05, f2 = f1 * f1, f4 = f2 * f2;
            float c1 = __cosf(0.5f * r);                     // Chebyshev chain
            float c2 = fmaf(2.f * c1, c1, -1.f);
            float c3 = fmaf(2.f * c1, c2, -c1);
            float c4 = fmaf(2.f * c1, c3, -c2);
            rad[0] += fc;
            rad[1] += e05 * fc;  rad[2] += e1g2 * fc;  rad[3] += e2g2 * fc;  rad[4] += e4g2 * fc;
            rad[5] += f05 * fc;  rad[6] += f1 * fc;    rad[7] += f2 * fc;    rad[8] += f4 * fc;
            rad[9] += c1 * fc;   rad[10] += c2 * fc;   rad[11] += c3 * fc;   rad[12] += c4 * fc;
            // neighbor data for angular phase
            sdx[j] = dx; sdy[j] = dy; sdz[j] = dz;
            sr2[j] = r2; sfc[j] = fc;
            se1[j] = __expf(-0.1f * r2);
            se5[j] = e05;
            sir[j] = rs;
        }
    }

    #pragma unroll
    for (int q = 0; q < 13; q++) {
        float v = rad[q];
        #pragma unroll
        for (int off = 16; off > 0; off >>= 1) v += __shfl_down_sync(0xffffffffu, v, off);
        if (lane == 0) sRedA[warp * 13 + q] = v;
    }
    __syncthreads();

    // ---- Build compacted index list (fully parallel) ----
    unsigned mw[NCHUNK];
    #pragma unroll
    for (int w = 0; w < NCHUNK; w++) mw[w] = smask[w];
    int M = 0;
    #pragma unroll
    for (int w = 0; w < NCHUNK; w++) M += __popc(mw[w]);

    for (int j = tid; j < N_ATOMS; j += NTHREADS) {
        int c = j >> 5;
        unsigned m = mw[c];
        if (m & (1u << (j & 31))) {
            int pos = __popc(m & ((1u << (j & 31)) - 1u));
            #pragma unroll
            for (int w = 0; w < NCHUNK; w++) if (w < c) pos += __popc(mw[w]);
            slist[pos] = j;
        }
    }
    __syncthreads();

    // ---- Phase 2: angular sums over unordered pairs a>b ----
    float s[8];
    #pragma unroll
    for (int q = 0; q < 8; q++) s[q] = 0.f;

    const int npairs = (M * (M - 1)) >> 1;
    for (int p = tid; p < npairs; p += NTHREADS) {
        // triangular index: p = a*(a-1)/2 + b, a>b
        int a = (int)((1.0f + sqrtf(fmaf(8.0f, (float)p, 1.0f))) * 0.5f);
        while (((a * (a - 1)) >> 1) > p) a--;
        while ((((a + 1) * a) >> 1) <= p) a++;
        int b = p - ((a * (a - 1)) >> 1);
        int ja = slist[a], jb = slist[b];

        float dot = sdx[ja] * sdx[jb] + sdy[ja] * sdy[jb] + sdz[ja] * sdz[jb];
        float cosv = dot * sir[ja] * sir[jb];
        float R2p  = sr2[ja] + sr2[jb];
        float r2jk = fmaxf(fmaf(-2.0f, dot, R2p), 0.0f);

        float fcjk = (r2jk < 36.0f)
                   ? 0.5f * (cos_sqrt_poly(PI2_36 * r2jk) + 1.0f) : 0.0f;

        float ejk1 = __expf(-0.1f * r2jk);
        float t2 = ejk1 * ejk1, t4 = t2 * t2;
        float ejk5 = t4 * ejk1;                       // exp(-0.5 r2jk)

        float ep1 = se1[ja] * se1[jb];
        float ep5 = se5[ja] * se5[jb];
        float fc2 = sfc[ja] * sfc[jb];
        float fc3 = fc2 * fcjk;
        float et1 = ep1 * ejk1, et5 = ep5 * ejk5;

        float op = 1.0f + cosv, om = 1.0f - cosv;
        float a1 = om * om;          // (1-c)^2
        float op2 = op * op;
        float a2 = op2 * op2;        // (1+c)^4
        float a3 = a1 * a1;          // (1-c)^4

        float w41 = et1 * fc3, w45 = et5 * fc3;
        float w51 = ep1 * fc2, w55 = ep5 * fc2;
        s[0] += op * w41; s[1] += a1 * w41; s[2] += a2 * w45; s[3] += a3 * w45;
        s[4] += op * w51; s[5] += a1 * w51; s[6] += a2 * w55; s[7] += a3 * w55;
    }

    #pragma unroll
    for (int q = 0; q < 8; q++) {
        float v = s[q];
        #pragma unroll
        for (int off = 16; off > 0; off >>= 1) v += __shfl_down_sync(0xffffffffu, v, off);
        if (lane == 0) sRedB[warp * 8 + q] = v;
    }
    __syncthreads();

    // ---- Output: 22 columns, one thread each ----
    if (tid == 0) out[i * 22 + 0] = atomic_numbers[i];
    if (tid >= 1 && tid < 14) {
        int q = tid - 1;
        float v = 0.f;
        #pragma unroll
        for (int w = 0; w < NWARPS; w++) v += sRedA[w * 13 + q];
        out[i * 22 + tid] = v;
    }
    if (tid >= 14 && tid < 22) {
        int q = tid - 14;
        const float scl[4] = {1.0f, 0.5f, 0.125f, 0.125f};  // 2^(1-zeta), unordered sum
        float v = 0.f;
        #pragma unroll
        for (int w = 0; w < NWARPS; w++) v += sRedB[w * 8 + q];
        out[i * 22 + tid] = v * scl[q & 3];
    }
}

extern "C" void kernel_launch(void* const* d_in, const int* in_sizes, int n_in,
                              void* d_out, int out_size)
{
    const float* atomic_numbers = (const float*)d_in[0]; // [320,1]
    const float* coordinates    = (const float*)d_in[1]; // [320,3]
    float* out = (float*)d_out;                          // [320,22]
    featurizer_kernel<<<N_ATOMS, NTHREADS>>>(atomic_numbers, coordinates, out);
}